// round 1
// baseline (speedup 1.0000x reference)
#include <cuda_runtime.h>
#include <stdint.h>

// ---------------- Problem constants (fixed dataset) ----------------
#define NMAX 100000
#define EMAX 1600000
#define DIM_IN  512
#define DIM_HID 128
#define DIM_OUT 64

// ---------------- Device scratch (no allocations allowed) ----------------
__device__ float g_bufA[(size_t)NMAX * DIM_HID];   // gemm outputs (also gemm2 out, 100k x 64)
__device__ float g_bufB[(size_t)NMAX * DIM_HID];   // spmm outputs
__device__ int   g_deg[NMAX];
__device__ int   g_cnt[NMAX];
__device__ int   g_rowptr[NMAX + 1];
__device__ int   g_ecol[EMAX];
__device__ float g_eval[EMAX];

// ---------------- CSR build ----------------
__global__ void zero_counts_kernel(int n) {
    int i = blockIdx.x * blockDim.x + threadIdx.x;
    if (i < n) { g_deg[i] = 0; g_cnt[i] = 0; }
}

__global__ void hist_kernel(const int* __restrict__ rows, int E) {
    int i = blockIdx.x * blockDim.x + threadIdx.x;
    if (i < E) atomicAdd(&g_deg[rows[i]], 1);
}

// Single-block exclusive scan over g_deg -> g_rowptr. blockDim must be 1024.
__global__ void scan_kernel(int n) {
    __shared__ int warpsums[32];
    __shared__ int s_carry;
    int tid = threadIdx.x, lane = tid & 31, wid = tid >> 5;
    if (tid == 0) s_carry = 0;
    __syncthreads();
    for (int base = 0; base < n; base += 1024) {
        int i = base + tid;
        int v = (i < n) ? g_deg[i] : 0;
        int x = v;
        #pragma unroll
        for (int o = 1; o < 32; o <<= 1) {
            int y = __shfl_up_sync(0xffffffffu, x, o);
            if (lane >= o) x += y;
        }
        if (lane == 31) warpsums[wid] = x;
        __syncthreads();
        if (wid == 0) {
            int s = warpsums[lane];
            #pragma unroll
            for (int o = 1; o < 32; o <<= 1) {
                int y = __shfl_up_sync(0xffffffffu, s, o);
                if (lane >= o) s += y;
            }
            warpsums[lane] = s;
        }
        __syncthreads();
        int pref = (wid > 0) ? warpsums[wid - 1] : 0;
        int carry = s_carry;
        int incl = x + pref + carry;
        if (i < n) g_rowptr[i] = incl - v;   // exclusive prefix
        __syncthreads();
        if (tid == 1023) s_carry = incl;
        __syncthreads();
    }
    if (tid == 0) g_rowptr[n] = s_carry;
}

__global__ void scatter_kernel(const int* __restrict__ rows,
                               const int* __restrict__ cols,
                               const float* __restrict__ vals, int E) {
    int i = blockIdx.x * blockDim.x + threadIdx.x;
    if (i < E) {
        int r = rows[i];
        int p = g_rowptr[r] + atomicAdd(&g_cnt[r], 1);
        g_ecol[p] = cols[i];
        g_eval[p] = vals[i];
    }
}

// ---------------- Dense GEMM: C[M,BN] = A[M,K] * W[BN,K]^T ----------------
// Classic register-blocked SGEMM. One block covers the full N (= BN) width.
template <int BM, int BN, int BK, int TM, int TN>
__global__ void sgemm_kernel(const float* __restrict__ A,
                             const float* __restrict__ W,
                             float* __restrict__ C, int M, int K) {
    constexpr int NT = (BM / TM) * (BN / TN);
    __shared__ float As[BK][BM];
    __shared__ float Bs[BK][BN];

    int tid = threadIdx.x;
    int m0  = blockIdx.x * BM;
    int tCol = tid % (BN / TN);
    int tRow = tid / (BN / TN);

    float acc[TM][TN];
    #pragma unroll
    for (int i = 0; i < TM; i++)
        #pragma unroll
        for (int j = 0; j < TN; j++) acc[i][j] = 0.f;

    for (int k0 = 0; k0 < K; k0 += BK) {
        // load A tile (BM x BK), transposed into As[k][m]
        #pragma unroll
        for (int idx = tid; idx < BM * BK / 4; idx += NT) {
            int r = idx / (BK / 4);
            int c = (idx % (BK / 4)) * 4;
            int row = m0 + r;
            float4 v = make_float4(0.f, 0.f, 0.f, 0.f);
            if (row < M) v = *(const float4*)(A + (size_t)row * K + k0 + c);
            As[c + 0][r] = v.x; As[c + 1][r] = v.y;
            As[c + 2][r] = v.z; As[c + 3][r] = v.w;
        }
        // load W tile: Bs[k][n] = W[n][k0+k]
        #pragma unroll
        for (int idx = tid; idx < BN * BK / 4; idx += NT) {
            int nrow = idx / (BK / 4);
            int c = (idx % (BK / 4)) * 4;
            float4 v = *(const float4*)(W + (size_t)nrow * K + k0 + c);
            Bs[c + 0][nrow] = v.x; Bs[c + 1][nrow] = v.y;
            Bs[c + 2][nrow] = v.z; Bs[c + 3][nrow] = v.w;
        }
        __syncthreads();
        #pragma unroll
        for (int k = 0; k < BK; k++) {
            float a[TM], b[TN];
            #pragma unroll
            for (int i = 0; i < TM; i++) a[i] = As[k][tRow * TM + i];
            #pragma unroll
            for (int j = 0; j < TN; j++) b[j] = Bs[k][tCol * TN + j];
            #pragma unroll
            for (int i = 0; i < TM; i++)
                #pragma unroll
                for (int j = 0; j < TN; j++) acc[i][j] += a[i] * b[j];
        }
        __syncthreads();
    }
    // store
    #pragma unroll
    for (int i = 0; i < TM; i++) {
        int row = m0 + tRow * TM + i;
        if (row < M) {
            float* cp = C + (size_t)row * BN + tCol * TN;
            #pragma unroll
            for (int j = 0; j < TN; j += 4) {
                float4 v = make_float4(acc[i][j], acc[i][j + 1],
                                       acc[i][j + 2], acc[i][j + 3]);
                *(float4*)(cp + j) = v;
            }
        }
    }
}

// ---------------- SpMM (CSR, warp per row) ----------------
// out[r,:] = sum over CSR edges of row r: val * h[col,:]; optional ReLU.
template <int WIDTH, bool RELU>
__global__ void spmm_kernel(const float* __restrict__ h,
                            float* __restrict__ out, int n) {
    int warp = (blockIdx.x * blockDim.x + threadIdx.x) >> 5;
    int lane = threadIdx.x & 31;
    if (warp >= n) return;
    int s = g_rowptr[warp];
    int e = g_rowptr[warp + 1];

    if (WIDTH == 128) {
        float4 acc = make_float4(0.f, 0.f, 0.f, 0.f);
        for (int i = s; i < e; i++) {
            int   c = g_ecol[i];
            float v = g_eval[i];
            float4 hv = __ldg((const float4*)(h + (size_t)c * 128) + lane);
            acc.x += v * hv.x; acc.y += v * hv.y;
            acc.z += v * hv.z; acc.w += v * hv.w;
        }
        if (RELU) {
            acc.x = fmaxf(acc.x, 0.f); acc.y = fmaxf(acc.y, 0.f);
            acc.z = fmaxf(acc.z, 0.f); acc.w = fmaxf(acc.w, 0.f);
        }
        ((float4*)(out + (size_t)warp * 128))[lane] = acc;
    } else {  // WIDTH == 64
        float2 acc = make_float2(0.f, 0.f);
        for (int i = s; i < e; i++) {
            int   c = g_ecol[i];
            float v = g_eval[i];
            float2 hv = __ldg((const float2*)(h + (size_t)c * 64) + lane);
            acc.x += v * hv.x; acc.y += v * hv.y;
        }
        if (RELU) { acc.x = fmaxf(acc.x, 0.f); acc.y = fmaxf(acc.y, 0.f); }
        ((float2*)(out + (size_t)warp * 64))[lane] = acc;
    }
}

// ---------------- Launcher ----------------
extern "C" void kernel_launch(void* const* d_in, const int* in_sizes, int n_in,
                              void* d_out, int out_size) {
    const float* x    = (const float*)d_in[0];
    const int*   rows = (const int*)  d_in[1];
    const int*   cols = (const int*)  d_in[2];
    const float* vals = (const float*)d_in[3];
    const float* W0   = (const float*)d_in[4];
    const float* W1   = (const float*)d_in[5];
    const float* W2   = (const float*)d_in[6];
    float* out = (float*)d_out;

    int n = in_sizes[0] / DIM_IN;   // 100000
    int E = in_sizes[1];            // 1600000

    float* bufA; float* bufB;
    cudaGetSymbolAddress((void**)&bufA, g_bufA);
    cudaGetSymbolAddress((void**)&bufB, g_bufB);

    // ---- CSR build (reused by all three SpMMs) ----
    zero_counts_kernel<<<(n + 255) / 256, 256>>>(n);
    hist_kernel<<<(E + 255) / 256, 256>>>(rows, E);
    scan_kernel<<<1, 1024>>>(n);
    scatter_kernel<<<(E + 255) / 256, 256>>>(rows, cols, vals, E);

    int gemmGrid = (n + 127) / 128;
    int spmmGrid = (n + 7) / 8;     // 8 warps per 256-thread block

    // layer 0: x @ W0^T -> spmm -> relu
    sgemm_kernel<128, 128, 16, 8, 8><<<gemmGrid, 256>>>(x, W0, bufA, n, DIM_IN);
    spmm_kernel<128, true><<<spmmGrid, 256>>>(bufA, bufB, n);

    // layer 1: h @ W1^T -> spmm -> relu
    sgemm_kernel<128, 128, 16, 8, 8><<<gemmGrid, 256>>>(bufB, W1, bufA, n, DIM_HID);
    spmm_kernel<128, true><<<spmmGrid, 256>>>(bufA, bufB, n);

    // layer 2: h @ W2^T -> spmm (no relu)
    sgemm_kernel<128, 64, 16, 8, 8><<<gemmGrid, 128>>>(bufB, W2, bufA, n, DIM_HID);
    spmm_kernel<64, false><<<spmmGrid, 256>>>(bufA, out, n);
}

// round 3
// speedup vs baseline: 1.8744x; 1.8744x over previous
#include <cuda_runtime.h>
#include <cuda_bf16.h>
#include <stdint.h>

// ---------------- Problem constants (fixed dataset) ----------------
#define NMAX 100000
#define EMAX 1600000
#define DIM_IN  512
#define DIM_HID 128
#define DIM_OUT 64

// ---------------- Device scratch (no allocations allowed) ----------------
__device__ float g_bufA[(size_t)NMAX * DIM_HID];   // gemm outputs
__device__ float g_bufB[(size_t)NMAX * DIM_HID];   // spmm outputs
__device__ int   g_deg[NMAX];
__device__ int   g_cnt[NMAX];
__device__ int   g_rowptr[NMAX + 1];
__device__ int   g_ecol[EMAX];
__device__ float g_eval[EMAX];

// ---------------- helpers ----------------
__device__ __forceinline__ uint32_t smem_u32(const void* p) {
    uint32_t a;
    asm("{ .reg .u64 t; cvta.to.shared.u64 t, %1; cvt.u32.u64 %0, t; }" : "=r"(a) : "l"(p));
    return a;
}
__device__ __forceinline__ uint32_t sw128(uint32_t b) { return b ^ ((b >> 3) & 0x70); }

__device__ __forceinline__ void ldsm_x4(uint32_t* r, uint32_t addr) {
    asm volatile("ldmatrix.sync.aligned.m8n8.x4.shared.b16 {%0,%1,%2,%3}, [%4];"
                 : "=r"(r[0]), "=r"(r[1]), "=r"(r[2]), "=r"(r[3]) : "r"(addr));
}
__device__ __forceinline__ void mma16816(float* d, const uint32_t* a, const uint32_t* b) {
    asm volatile(
        "mma.sync.aligned.m16n8k16.row.col.f32.bf16.bf16.f32 "
        "{%0,%1,%2,%3}, {%4,%5,%6,%7}, {%8,%9}, {%0,%1,%2,%3};"
        : "+f"(d[0]), "+f"(d[1]), "+f"(d[2]), "+f"(d[3])
        : "r"(a[0]), "r"(a[1]), "r"(a[2]), "r"(a[3]), "r"(b[0]), "r"(b[1]));
}

// fp32 -> (hi, lo) bf16 pairs, 4 floats at a time
__device__ __forceinline__ void cvt_hilo(float4 v, uint2& hi, uint2& lo) {
    __nv_bfloat162 h01 = __floats2bfloat162_rn(v.x, v.y);
    __nv_bfloat162 h23 = __floats2bfloat162_rn(v.z, v.w);
    __nv_bfloat162 l01 = __floats2bfloat162_rn(v.x - __bfloat162float(h01.x),
                                               v.y - __bfloat162float(h01.y));
    __nv_bfloat162 l23 = __floats2bfloat162_rn(v.z - __bfloat162float(h23.x),
                                               v.w - __bfloat162float(h23.y));
    hi = make_uint2(*(uint32_t*)&h01, *(uint32_t*)&h23);
    lo = make_uint2(*(uint32_t*)&l01, *(uint32_t*)&l23);
}

// ---------------- CSR build ----------------
__global__ void zero_counts_kernel(int n) {
    int i = blockIdx.x * blockDim.x + threadIdx.x;
    if (i < n) { g_deg[i] = 0; g_cnt[i] = 0; }
}

__global__ void hist_kernel(const int* __restrict__ rows, int E) {
    int i = blockIdx.x * blockDim.x + threadIdx.x;
    if (i < E) atomicAdd(&g_deg[rows[i]], 1);
}

// Single-block exclusive scan over g_deg -> g_rowptr. blockDim must be 1024.
__global__ void scan_kernel(int n) {
    __shared__ int warpsums[32];
    __shared__ int s_carry;
    int tid = threadIdx.x, lane = tid & 31, wid = tid >> 5;
    if (tid == 0) s_carry = 0;
    __syncthreads();
    for (int base = 0; base < n; base += 1024) {
        int i = base + tid;
        int v = (i < n) ? g_deg[i] : 0;
        int x = v;
        #pragma unroll
        for (int o = 1; o < 32; o <<= 1) {
            int y = __shfl_up_sync(0xffffffffu, x, o);
            if (lane >= o) x += y;
        }
        if (lane == 31) warpsums[wid] = x;
        __syncthreads();
        if (wid == 0) {
            int s = warpsums[lane];
            #pragma unroll
            for (int o = 1; o < 32; o <<= 1) {
                int y = __shfl_up_sync(0xffffffffu, s, o);
                if (lane >= o) s += y;
            }
            warpsums[lane] = s;
        }
        __syncthreads();
        int pref = (wid > 0) ? warpsums[wid - 1] : 0;
        int carry = s_carry;
        int incl = x + pref + carry;
        if (i < n) g_rowptr[i] = incl - v;   // exclusive prefix
        __syncthreads();
        if (tid == 1023) s_carry = incl;
        __syncthreads();
    }
    if (tid == 0) g_rowptr[n] = s_carry;
}

__global__ void scatter_kernel(const int* __restrict__ rows,
                               const int* __restrict__ cols,
                               const float* __restrict__ vals, int E) {
    int i = blockIdx.x * blockDim.x + threadIdx.x;
    if (i < E) {
        int r = rows[i];
        int p = g_rowptr[r] + atomicAdd(&g_cnt[r], 1);
        g_ecol[p] = cols[i];
        g_eval[p] = vals[i];
    }
}

// ---------------- Tensor-core GEMM via mma.sync ----------------
// C[M,BN] = A[M,K] * W[BN,K]^T, fp32 emulated by bf16 hi/lo split:
//   D += Ahi*Bhi + Ahi*Blo + Alo*Bhi   (error ~2^-16, well under 1e-3)
// Each K-chunk = 32 fp32 -> smem rows of 128 bytes: [hi 32xbf16 | lo 32xbf16],
// SW128 swizzle (conflict-free ldmatrix). Double-buffered.
template <int BM, int BN, int WM, int WN, int K>
__global__ void __launch_bounds__(WM * WN * 32, 1)
mma_gemm_kernel(const float* __restrict__ A, const float* __restrict__ W,
                float* __restrict__ C, int M)
{
    constexpr int THREADS = WM * WN * 32;
    constexpr int NCHUNK  = K / 32;
    constexpr int ASZ = BM * 128;          // bytes per A buffer
    constexpr int BSZ = BN * 128;          // bytes per B buffer
    constexpr int AL  = BM * 8 / THREADS;  // float4 loads per thread (A)
    constexpr int BL  = BN * 8 / THREADS;  // float4 loads per thread (B)
    constexpr int MT  = BM / WM / 16;      // m16 tiles per warp
    constexpr int NT  = BN / WN / 8;       // n8  tiles per warp

    extern __shared__ __align__(1024) char smem[];
    const uint32_t sb = smem_u32(smem);

    const int tid = threadIdx.x;
    const int l   = tid & 31;
    const int w   = tid >> 5;
    const int wmBase = (w % WM) * (BM / WM);
    const int wnBase = (w / WM) * (BN / WN);
    const int m0 = blockIdx.x * BM;

    float acc[MT][NT][4];
    #pragma unroll
    for (int i = 0; i < MT; i++)
        #pragma unroll
        for (int j = 0; j < NT; j++)
            #pragma unroll
            for (int q = 0; q < 4; q++) acc[i][j][q] = 0.f;

    float4 regA[AL], regB[BL];

    // lane-derived ldmatrix addressing components
    const int arow = l & 15;                       // A tile row within 16
    const int acol = (l & 16) ? 16 : 0;            // A k8-group byte offset
    const int brow = ((l & 16) ? 8 : 0) + (l & 7); // B row (2 n8-tiles per x4)
    const int bcol = (l & 8) ? 16 : 0;             // B k8-group byte offset

    auto loadChunk = [&](int c) {
        const int k0 = c * 32;
        #pragma unroll
        for (int i = 0; i < AL; i++) {
            int idx = tid + i * THREADS;
            int r = idx >> 3, c4 = (idx & 7) << 2;
            int row = m0 + r; if (row >= M) row = M - 1;
            regA[i] = __ldg((const float4*)(A + (size_t)row * K + k0 + c4));
        }
        #pragma unroll
        for (int i = 0; i < BL; i++) {
            int idx = tid + i * THREADS;
            int r = idx >> 3, c4 = (idx & 7) << 2;
            regB[i] = __ldg((const float4*)(W + (size_t)r * K + k0 + c4));
        }
    };

    auto stsChunk = [&](int b) {
        char* abase = smem + b * (ASZ + BSZ);
        char* bbase = abase + ASZ;
        #pragma unroll
        for (int i = 0; i < AL; i++) {
            int idx = tid + i * THREADS;
            int r = idx >> 3, c4 = (idx & 7) << 2;
            uint2 hi, lo; cvt_hilo(regA[i], hi, lo);
            *(uint2*)(abase + sw128((uint32_t)(r * 128 + c4 * 2)))      = hi;
            *(uint2*)(abase + sw128((uint32_t)(r * 128 + 64 + c4 * 2))) = lo;
        }
        #pragma unroll
        for (int i = 0; i < BL; i++) {
            int idx = tid + i * THREADS;
            int r = idx >> 3, c4 = (idx & 7) << 2;
            uint2 hi, lo; cvt_hilo(regB[i], hi, lo);
            *(uint2*)(bbase + sw128((uint32_t)(r * 128 + c4 * 2)))      = hi;
            *(uint2*)(bbase + sw128((uint32_t)(r * 128 + 64 + c4 * 2))) = lo;
        }
    };

    auto compute = [&](int b) {
        const uint32_t sA = sb + b * (ASZ + BSZ);
        const uint32_t sB = sA + ASZ;
        #pragma unroll
        for (int kg = 0; kg < 2; kg++) {
            const int kb = kg * 32;
            uint32_t aH[MT][4], aLo[MT][4];
            #pragma unroll
            for (int mt = 0; mt < MT; mt++) {
                uint32_t rowb = (uint32_t)((wmBase + mt * 16 + arow) * 128);
                ldsm_x4(aH[mt],  sA + sw128(rowb + kb + acol));
                ldsm_x4(aLo[mt], sA + sw128(rowb + 64 + kb + acol));
            }
            uint32_t bH[NT][2], bLo[NT][2];
            #pragma unroll
            for (int nt = 0; nt < NT; nt += 2) {
                uint32_t rowb = (uint32_t)((wnBase + nt * 8 + brow) * 128);
                uint32_t t[4];
                ldsm_x4(t, sB + sw128(rowb + kb + bcol));
                bH[nt][0] = t[0]; bH[nt][1] = t[1];
                bH[nt + 1][0] = t[2]; bH[nt + 1][1] = t[3];
                ldsm_x4(t, sB + sw128(rowb + 64 + kb + bcol));
                bLo[nt][0] = t[0]; bLo[nt][1] = t[1];
                bLo[nt + 1][0] = t[2]; bLo[nt + 1][1] = t[3];
            }
            #pragma unroll
            for (int mt = 0; mt < MT; mt++)
                #pragma unroll
                for (int nt = 0; nt < NT; nt++) {
                    mma16816(acc[mt][nt], aH[mt],  bH[nt]);
                    mma16816(acc[mt][nt], aH[mt],  bLo[nt]);
                    mma16816(acc[mt][nt], aLo[mt], bH[nt]);
                }
        }
    };

    // prologue
    loadChunk(0);
    stsChunk(0);
    __syncthreads();

    for (int c = 0; c < NCHUNK; c++) {
        if (c + 1 < NCHUNK) loadChunk(c + 1);
        compute(c & 1);
        if (c + 1 < NCHUNK) {
            __syncthreads();          // everyone done reading buf (c+1)&1 from iter c-1
            stsChunk((c + 1) & 1);
            __syncthreads();
        }
    }

    // epilogue: write fp32 accumulators
    #pragma unroll
    for (int mt = 0; mt < MT; mt++) {
        int m = m0 + wmBase + mt * 16 + (l >> 2);
        #pragma unroll
        for (int nt = 0; nt < NT; nt++) {
            int nn = wnBase + nt * 8 + ((l & 3) << 1);
            if (m < M)
                *(float2*)(C + (size_t)m * BN + nn) =
                    make_float2(acc[mt][nt][0], acc[mt][nt][1]);
            if (m + 8 < M)
                *(float2*)(C + (size_t)(m + 8) * BN + nn) =
                    make_float2(acc[mt][nt][2], acc[mt][nt][3]);
        }
    }
}

// ---------------- SpMM (CSR, warp per row) ----------------
template <int WIDTH, bool RELU>
__global__ void spmm_kernel(const float* __restrict__ h,
                            float* __restrict__ out, int n) {
    int warp = (blockIdx.x * blockDim.x + threadIdx.x) >> 5;
    int lane = threadIdx.x & 31;
    if (warp >= n) return;
    int s = g_rowptr[warp];
    int e = g_rowptr[warp + 1];

    if (WIDTH == 128) {
        float4 acc = make_float4(0.f, 0.f, 0.f, 0.f);
        for (int i = s; i < e; i++) {
            int   c = g_ecol[i];
            float v = g_eval[i];
            float4 hv = __ldg((const float4*)(h + (size_t)c * 128) + lane);
            acc.x += v * hv.x; acc.y += v * hv.y;
            acc.z += v * hv.z; acc.w += v * hv.w;
        }
        if (RELU) {
            acc.x = fmaxf(acc.x, 0.f); acc.y = fmaxf(acc.y, 0.f);
            acc.z = fmaxf(acc.z, 0.f); acc.w = fmaxf(acc.w, 0.f);
        }
        ((float4*)(out + (size_t)warp * 128))[lane] = acc;
    } else {  // WIDTH == 64
        float2 acc = make_float2(0.f, 0.f);
        for (int i = s; i < e; i++) {
            int   c = g_ecol[i];
            float v = g_eval[i];
            float2 hv = __ldg((const float2*)(h + (size_t)c * 64) + lane);
            acc.x += v * hv.x; acc.y += v * hv.y;
        }
        if (RELU) { acc.x = fmaxf(acc.x, 0.f); acc.y = fmaxf(acc.y, 0.f); }
        ((float2*)(out + (size_t)warp * 64))[lane] = acc;
    }
}

// ---------------- Launcher ----------------
extern "C" void kernel_launch(void* const* d_in, const int* in_sizes, int n_in,
                              void* d_out, int out_size) {
    const float* x    = (const float*)d_in[0];
    const int*   rows = (const int*)  d_in[1];
    const int*   cols = (const int*)  d_in[2];
    const float* vals = (const float*)d_in[3];
    const float* W0   = (const float*)d_in[4];
    const float* W1   = (const float*)d_in[5];
    const float* W2   = (const float*)d_in[6];
    float* out = (float*)d_out;

    int n = in_sizes[0] / DIM_IN;   // 100000
    int E = in_sizes[1];            // 1600000

    float* bufA; float* bufB;
    cudaGetSymbolAddress((void**)&bufA, g_bufA);
    cudaGetSymbolAddress((void**)&bufB, g_bufB);

    // smem: double-buffered (A + B) tiles
    const int smem0 = 2 * (128 * 128 + 128 * 128);  // 64 KB (BN=128)
    const int smem2 = 2 * (128 * 128 + 64 * 128);   // 48 KB (BN=64)
    cudaFuncSetAttribute(mma_gemm_kernel<128, 128, 2, 4, 512>,
                         cudaFuncAttributeMaxDynamicSharedMemorySize, smem0);
    cudaFuncSetAttribute(mma_gemm_kernel<128, 128, 2, 4, 128>,
                         cudaFuncAttributeMaxDynamicSharedMemorySize, smem0);
    cudaFuncSetAttribute(mma_gemm_kernel<128, 64, 4, 2, 128>,
                         cudaFuncAttributeMaxDynamicSharedMemorySize, smem2);

    // ---- CSR build (reused by all three SpMMs) ----
    zero_counts_kernel<<<(n + 255) / 256, 256>>>(n);
    hist_kernel<<<(E + 255) / 256, 256>>>(rows, E);
    scan_kernel<<<1, 1024>>>(n);
    scatter_kernel<<<(E + 255) / 256, 256>>>(rows, cols, vals, E);

    int gemmGrid = (n + 127) / 128;
    int spmmGrid = (n + 7) / 8;     // 8 warps per 256-thread block

    // layer 0: x @ W0^T -> spmm -> relu
    mma_gemm_kernel<128, 128, 2, 4, 512><<<gemmGrid, 256, smem0>>>(x, W0, bufA, n);
    spmm_kernel<128, true><<<spmmGrid, 256>>>(bufA, bufB, n);

    // layer 1: h @ W1^T -> spmm -> relu
    mma_gemm_kernel<128, 128, 2, 4, 128><<<gemmGrid, 256, smem0>>>(bufB, W1, bufA, n);
    spmm_kernel<128, true><<<spmmGrid, 256>>>(bufA, bufB, n);

    // layer 2: h @ W2^T -> spmm (no relu)
    mma_gemm_kernel<128, 64, 4, 2, 128><<<gemmGrid, 256, smem2>>>(bufB, W2, bufA, n);
    spmm_kernel<64, false><<<spmmGrid, 256>>>(bufA, out, n);
}